// round 16
// baseline (speedup 1.0000x reference)
#include <cuda_runtime.h>
#include <cuda_fp16.h>
#include <math.h>

// Problem constants
#define C_DIM   1024
#define HEADS   16
#define HD      64
#define BATCH   2
#define SEQ     2048
#define M_ROWS  (BATCH*SEQ)        // 4096

// Scratch (device globals: no allocation allowed)
__device__ float  g_qkv[(size_t)M_ROWS * 3 * C_DIM];          // [4096, 3072] fp32
__device__ __half g_Qh[(size_t)BATCH*HEADS*SEQ*HD];           // [B,H,N,D] fp16, pre-scaled 0.125*log2e
__device__ __half g_Kh[(size_t)BATCH*HEADS*SEQ*HD];
__device__ __half g_Vh[(size_t)BATCH*HEADS*SEQ*HD];
__device__ __half g_attnh[(size_t)M_ROWS * C_DIM];            // [B,N,H*D] fp16
__device__ __half g_xh[(size_t)M_ROWS * C_DIM];               // x fp16
__device__ __half g_wqkvh[(size_t)3 * C_DIM * C_DIM];         // Wqkv fp16
__device__ __half g_wouth[(size_t)C_DIM * C_DIM];             // Wout fp16
__device__ float  g_cos[SEQ * 32];
__device__ float  g_sin[SEQ * 32];

// ---------------------------------------------------------------------------
// helpers
// ---------------------------------------------------------------------------
__device__ __forceinline__ unsigned pack_h2(float lo, float hi) {
    unsigned r;
    asm("cvt.rn.f16x2.f32 %0, %1, %2;" : "=r"(r) : "f"(hi), "f"(lo));
    return r;
}

__device__ __forceinline__ float ex2(float x) {
    float r;
    asm("ex2.approx.f32 %0, %1;" : "=f"(r) : "f"(x));
    return r;
}

__device__ __forceinline__ void mma_f16(float* d, const unsigned* a, unsigned b0, unsigned b1) {
    asm volatile(
        "mma.sync.aligned.m16n8k16.row.col.f32.f16.f16.f32 "
        "{%0,%1,%2,%3}, {%4,%5,%6,%7}, {%8,%9}, {%0,%1,%2,%3};\n"
        : "+f"(d[0]), "+f"(d[1]), "+f"(d[2]), "+f"(d[3])
        : "r"(a[0]), "r"(a[1]), "r"(a[2]), "r"(a[3]), "r"(b0), "r"(b1));
}

__device__ __forceinline__ void ldsm4(unsigned* r, unsigned addr) {
    asm volatile(
        "ldmatrix.sync.aligned.m8n8.x4.shared.b16 {%0,%1,%2,%3}, [%4];"
        : "=r"(r[0]), "=r"(r[1]), "=r"(r[2]), "=r"(r[3]) : "r"(addr));
}
__device__ __forceinline__ void ldsm4t(unsigned* r, unsigned addr) {
    asm volatile(
        "ldmatrix.sync.aligned.m8n8.x4.trans.shared.b16 {%0,%1,%2,%3}, [%4];"
        : "=r"(r[0]), "=r"(r[1]), "=r"(r[2]), "=r"(r[3]) : "r"(addr));
}

__device__ __forceinline__ void cp_async16(unsigned saddr, const void* gaddr) {
    asm volatile("cp.async.cg.shared.global [%0], [%1], 16;" :: "r"(saddr), "l"(gaddr));
}
#define CP_COMMIT() asm volatile("cp.async.commit_group;")
#define CP_WAIT1()  asm volatile("cp.async.wait_group 1;")

// ---------------------------------------------------------------------------
// Prep: fp32->fp16 for x/Wqkv/Wout + RoPE table, single launch (flat index)
// ---------------------------------------------------------------------------
#define N4_X   (M_ROWS * C_DIM / 4)           // 1048576
#define N4_WQ  (3 * C_DIM * C_DIM / 4)        // 786432
#define N4_WO  (C_DIM * C_DIM / 4)            // 262144
#define N4_ALL (N4_X + N4_WQ + N4_WO)
#define NTBL   (SEQ * 32)
#define NPREP  (N4_ALL + NTBL)

__global__ void prep_all(const float4* __restrict__ x,    __half2* __restrict__ xh,
                         const float4* __restrict__ wq,   __half2* __restrict__ wqh,
                         const float4* __restrict__ wo,   __half2* __restrict__ woh)
{
    int i = blockIdx.x * blockDim.x + threadIdx.x;
    if (i < N4_ALL) {
        const float4* in;
        __half2* out;
        if (i < N4_X)              { in = x;  out = xh; }
        else if (i < N4_X + N4_WQ) { in = wq; out = wqh; i -= N4_X; }
        else                       { in = wo; out = woh; i -= N4_X + N4_WQ; }
        float4 v = in[i];
        out[2 * i]     = __floats2half2_rn(v.x, v.y);
        out[2 * i + 1] = __floats2half2_rn(v.z, v.w);
    } else if (i < NPREP) {
        int idx = i - N4_ALL;
        int ii = idx & 31;
        int n  = idx >> 5;
        float inv_freq = (float)pow(10000.0, -(double)ii / 32.0);
        float phase = (float)n * inv_freq;
        g_cos[idx] = (float)cos((double)phase);
        g_sin[idx] = (float)sin((double)phase);
    }
}

// ---------------------------------------------------------------------------
// fp16 GEMM (NT), cp.async 3-stage pipelined, ldmatrix fragments.
// C[M,N](fp32) = A[M,K](fp16) * B[N,K]^T(fp16) (+ bias)
// ---------------------------------------------------------------------------
#define GBM 128
#define GBN 128
#define GBK 64
#define GSH 72
#define GSTAGE_BYTES ((GBM + GBN) * GSH * 2)    // 36864
#define GEMM_SMEM_BYTES (3 * GSTAGE_BYTES)      // 110592

__global__ __launch_bounds__(256, 2)
void gemm_f16_db(const __half* __restrict__ A, const __half* __restrict__ B,
                 float* __restrict__ C, int M, int N, int K,
                 const float* __restrict__ bias)
{
    extern __shared__ __half gsm[];

    const int tid  = threadIdx.x;
    const int lane = tid & 31;
    const int warp = tid >> 5;
    const int wm   = (warp >> 2) * 64;
    const int wn   = (warp & 3) * 32;
    const int m0   = blockIdx.y * GBM;
    const int n0   = blockIdx.x * GBN;
    const int lg   = lane >> 2;
    const int lt   = lane & 3;
    const int t8   = lane >> 3;
    const int rr   = lane & 7;

    const unsigned sBase = (unsigned)__cvta_generic_to_shared(gsm);

    unsigned aab[4];
#pragma unroll
    for (int mt = 0; mt < 4; mt++)
        aab[mt] = sBase + 2u * ((wm + mt * 16 + (t8 & 1) * 8 + rr) * GSH + (t8 >> 1) * 8);
    unsigned bbb[2];
#pragma unroll
    for (int ntp = 0; ntp < 2; ntp++)
        bbb[ntp] = sBase + (unsigned)(GBM * GSH * 2)
                 + 2u * ((wn + ntp * 16 + (t8 >> 1) * 8 + rr) * GSH + (t8 & 1) * 8);

    float acc[4][4][4];
#pragma unroll
    for (int mt = 0; mt < 4; mt++)
#pragma unroll
        for (int nt = 0; nt < 4; nt++)
#pragma unroll
            for (int j = 0; j < 4; j++) acc[mt][nt][j] = 0.f;

    const int T = K / GBK;

#pragma unroll
    for (int pt = 0; pt < 2; pt++) {
        if (pt < T) {
            const unsigned so = (unsigned)pt * GSTAGE_BYTES;
            const int k0 = pt * GBK;
#pragma unroll
            for (int i = 0; i < 4; i++) {
                int e = tid + i * 256;
                int r = e >> 3, c8 = (e & 7) << 3;
                cp_async16(sBase + so + 2u * (r * GSH + c8),
                           &A[(size_t)(m0 + r) * K + k0 + c8]);
                cp_async16(sBase + so + (unsigned)(GBM * GSH * 2) + 2u * (r * GSH + c8),
                           &B[(size_t)(n0 + r) * K + k0 + c8]);
            }
            CP_COMMIT();
        }
    }

    for (int t = 0; t < T; t++) {
        const unsigned soff = (unsigned)(t % 3) * GSTAGE_BYTES;
        CP_WAIT1();
        __syncthreads();

        if (t + 2 < T) {
            const unsigned snext = (unsigned)((t + 2) % 3) * GSTAGE_BYTES;
            const int k0 = (t + 2) * GBK;
#pragma unroll
            for (int i = 0; i < 4; i++) {
                int e = tid + i * 256;
                int r = e >> 3, c8 = (e & 7) << 3;
                cp_async16(sBase + snext + 2u * (r * GSH + c8),
                           &A[(size_t)(m0 + r) * K + k0 + c8]);
                cp_async16(sBase + snext + (unsigned)(GBM * GSH * 2) + 2u * (r * GSH + c8),
                           &B[(size_t)(n0 + r) * K + k0 + c8]);
            }
            CP_COMMIT();
        }

#pragma unroll
        for (int ks = 0; ks < 4; ks++) {
            unsigned af[4][4], bf[2][4];
#pragma unroll
            for (int mt = 0; mt < 4; mt++) ldsm4(af[mt], aab[mt] + soff + ks * 32);
#pragma unroll
            for (int ntp = 0; ntp < 2; ntp++) ldsm4(bf[ntp], bbb[ntp] + soff + ks * 32);
#pragma unroll
            for (int mt = 0; mt < 4; mt++)
#pragma unroll
                for (int nt = 0; nt < 4; nt++)
                    mma_f16(acc[mt][nt], af[mt],
                            bf[nt >> 1][(nt & 1) * 2], bf[nt >> 1][(nt & 1) * 2 + 1]);
        }
        __syncthreads();
    }

#pragma unroll
    for (int mt = 0; mt < 4; mt++) {
#pragma unroll
        for (int nt = 0; nt < 4; nt++) {
            int r = m0 + wm + mt * 16 + lg;
            int c = n0 + wn + nt * 8 + (lt << 1);
            float b0 = bias ? bias[c] : 0.f;
            float b1 = bias ? bias[c + 1] : 0.f;
            float2 v0 = make_float2(acc[mt][nt][0] + b0, acc[mt][nt][1] + b1);
            float2 v1 = make_float2(acc[mt][nt][2] + b0, acc[mt][nt][3] + b1);
            *(float2*)&C[(size_t)r * N + c]       = v0;
            *(float2*)&C[(size_t)(r + 8) * N + c] = v1;
        }
    }
}

// ---------------------------------------------------------------------------
// RoPE + transpose (pair-symmetric, vectorized). Q pre-scaled by 0.125*log2e.
// ---------------------------------------------------------------------------
#define QSCALE 0.18033688011112042f   // 0.125 * log2(e)

__global__ void rope_transpose(const float* __restrict__ qkv,
                               __half* __restrict__ Q, __half* __restrict__ K,
                               __half* __restrict__ V)
{
    int idx = blockIdx.x * blockDim.x + threadIdx.x;   // over B*H*N*16
    if (idx >= BATCH * HEADS * SEQ * 16) return;
    int i2 = idx & 15;
    int n  = (idx >> 4) & (SEQ - 1);
    int h  = (idx >> 15) & (HEADS - 1);
    int b  = idx >> 19;

    const size_t mrow = (size_t)(b * SEQ + n) * (3 * C_DIM);
    const int col = h * HD + 2 * i2;

    float2 qlo = *(const float2*)&qkv[mrow + col];
    float2 qhi = *(const float2*)&qkv[mrow + col + 32];
    float2 klo = *(const float2*)&qkv[mrow + C_DIM + col];
    float2 khi = *(const float2*)&qkv[mrow + C_DIM + col + 32];
    float2 vlo = *(const float2*)&qkv[mrow + 2 * C_DIM + col];
    float2 vhi = *(const float2*)&qkv[mrow + 2 * C_DIM + col + 32];

    float2 cc = *(const float2*)&g_cos[n * 32 + 2 * i2];
    float2 ss = *(const float2*)&g_sin[n * 32 + 2 * i2];

    size_t o = ((size_t)(b * HEADS + h) * SEQ + n) * HD + 2 * i2;

    *(__half2*)&Q[o]      = __floats2half2_rn((qlo.x * cc.x - qhi.x * ss.x) * QSCALE,
                                              (qlo.y * cc.y - qhi.y * ss.y) * QSCALE);
    *(__half2*)&Q[o + 32] = __floats2half2_rn((qhi.x * cc.x + qlo.x * ss.x) * QSCALE,
                                              (qhi.y * cc.y + qlo.y * ss.y) * QSCALE);
    *(__half2*)&K[o]      = __floats2half2_rn(klo.x * cc.x - khi.x * ss.x,
                                              klo.y * cc.y - khi.y * ss.y);
    *(__half2*)&K[o + 32] = __floats2half2_rn(khi.x * cc.x + klo.x * ss.x,
                                              khi.y * cc.y + klo.y * ss.y);
    *(__half2*)&V[o]      = __floats2half2_rn(vlo.x, vlo.y);
    *(__half2*)&V[o + 32] = __floats2half2_rn(vhi.x, vhi.y);
}

// ---------------------------------------------------------------------------
// Flash attention (R13-proven body + 3-stage KV pipeline):
//  - full fp16 mma, Q fragments hoisted, log2-domain batched softmax
//  - independent FADD row sums + shfl reductions (latency-hidden; the
//    ones-mma variant serialized the tensor pipe and regressed — do not redo)
// ---------------------------------------------------------------------------
#define QTILE 128
#define KTILE 64
#define STH   72
#define KV_STAGE  (2 * KTILE * STH * 2)           // 18432 (K + V)
#define KV_VOFF   (KTILE * STH * 2)               // 9216
#define ATTN_SMEM_BYTES (3 * KV_STAGE)            // 55296

__global__ __launch_bounds__(256)
void attn_f16(const __half* __restrict__ Q, const __half* __restrict__ K,
              const __half* __restrict__ V, __half* __restrict__ Out)
{
    extern __shared__ __half hsm[];

    const int tid  = threadIdx.x;
    const int lane = tid & 31;
    const int warp = tid >> 5;
    const int lg   = lane >> 2;
    const int lt   = lane & 3;
    const int t8   = lane >> 3;
    const int rr   = lane & 7;
    const int b = blockIdx.z, h = blockIdx.y;
    const int q0 = blockIdx.x * QTILE;
    const int qr = warp * 16;

    const unsigned sBase = (unsigned)__cvta_generic_to_shared(hsm);

    const __half* Qb = Q + (size_t)(b * HEADS + h) * SEQ * HD;
    const __half* Kb = K + (size_t)(b * HEADS + h) * SEQ * HD;
    const __half* Vb = V + (size_t)(b * HEADS + h) * SEQ * HD;

    const unsigned aQ = sBase + 2u * ((qr + (t8 & 1) * 8 + rr) * STH + (t8 >> 1) * 8);
    const unsigned kOff = 2u * (((t8 >> 1) * 8 + rr) * STH + (t8 & 1) * 8);
    const unsigned vOff = (unsigned)KV_VOFF + 2u * ((8 * (t8 & 1) + rr) * STH + 8 * (t8 >> 1));

    // Q tile fill into region 0
#pragma unroll
    for (int i = 0; i < 4; i++) {
        int e = tid + i * 256;
        int r = e >> 3, c8 = (e & 7) << 3;
        *(uint4*)&hsm[r * STH + c8] = *(const uint4*)&Qb[(size_t)(q0 + r) * HD + c8];
    }

    // Prefetch KV tiles 0 (region 1) and 1 (region 2)
#pragma unroll
    for (int pt = 0; pt < 2; pt++) {
        const unsigned st = sBase + (unsigned)(pt + 1) * KV_STAGE;
        const int k0 = pt * KTILE;
#pragma unroll
        for (int i = 0; i < 2; i++) {
            int e = tid + i * 256;
            int r = e >> 3, c8 = (e & 7) << 3;
            cp_async16(st + 2u * (r * STH + c8), &Kb[(size_t)(k0 + r) * HD + c8]);
            cp_async16(st + (unsigned)KV_VOFF + 2u * (r * STH + c8),
                       &Vb[(size_t)(k0 + r) * HD + c8]);
        }
        CP_COMMIT();
    }

    // Hoist Q fragments (frees region 0)
    __syncthreads();
    unsigned aq[4][4];
#pragma unroll
    for (int ks = 0; ks < 4; ks++) ldsm4(aq[ks], aQ + ks * 32);

    float o[8][4];
#pragma unroll
    for (int nt = 0; nt < 8; nt++)
#pragma unroll
        for (int j = 0; j < 4; j++) o[nt][j] = 0.f;
    float m_lo = -1e30f, m_hi = -1e30f, l_lo = 0.f, l_hi = 0.f;

    const int T = SEQ / KTILE;
    for (int t = 0; t < T; t++) {
        const unsigned st = sBase + (unsigned)((t + 1) % 3) * KV_STAGE;
        CP_WAIT1();
        __syncthreads();

        if (t + 2 < T) {
            const unsigned sn = sBase + (unsigned)((t + 3) % 3) * KV_STAGE;
            const int k0 = (t + 2) * KTILE;
#pragma unroll
            for (int i = 0; i < 2; i++) {
                int e = tid + i * 256;
                int r = e >> 3, c8 = (e & 7) << 3;
                cp_async16(sn + 2u * (r * STH + c8), &Kb[(size_t)(k0 + r) * HD + c8]);
                cp_async16(sn + (unsigned)KV_VOFF + 2u * (r * STH + c8),
                           &Vb[(size_t)(k0 + r) * HD + c8]);
            }
            CP_COMMIT();
        }

        // ---- S' = (log2e/8) Q K^T  (log2 domain) ----
        float s[8][4];
#pragma unroll
        for (int nt = 0; nt < 8; nt++)
#pragma unroll
            for (int j = 0; j < 4; j++) s[nt][j] = 0.f;

#pragma unroll
        for (int ks = 0; ks < 4; ks++) {
#pragma unroll
            for (int ntp = 0; ntp < 4; ntp++) {
                unsigned kf[4];
                ldsm4(kf, st + kOff + (unsigned)(ntp * 16 * STH * 2) + ks * 32);
                mma_f16(s[2 * ntp],     aq[ks], kf[0], kf[1]);
                mma_f16(s[2 * ntp + 1], aq[ks], kf[2], kf[3]);
            }
        }

        // ---- online softmax (log2 domain, batched phase) ----
        float rmax_lo = -1e30f, rmax_hi = -1e30f;
#pragma unroll
        for (int nt = 0; nt < 8; nt++) {
            rmax_lo = fmaxf(rmax_lo, fmaxf(s[nt][0], s[nt][1]));
            rmax_hi = fmaxf(rmax_hi, fmaxf(s[nt][2], s[nt][3]));
        }
        rmax_lo = fmaxf(rmax_lo, __shfl_xor_sync(0xffffffffu, rmax_lo, 1));
        rmax_lo = fmaxf(rmax_lo, __shfl_xor_sync(0xffffffffu, rmax_lo, 2));
        rmax_hi = fmaxf(rmax_hi, __shfl_xor_sync(0xffffffffu, rmax_hi, 1));
        rmax_hi = fmaxf(rmax_hi, __shfl_xor_sync(0xffffffffu, rmax_hi, 2));

        float mn_lo = fmaxf(m_lo, rmax_lo);
        float mn_hi = fmaxf(m_hi, rmax_hi);
        float alpha_lo = ex2(m_lo - mn_lo);
        float alpha_hi = ex2(m_hi - mn_hi);
        m_lo = mn_lo; m_hi = mn_hi;

        float sum_lo = 0.f, sum_hi = 0.f;
#pragma unroll
        for (int nt = 0; nt < 8; nt++) {
            s[nt][0] = ex2(s[nt][0] - m_lo);
            s[nt][1] = ex2(s[nt][1] - m_lo);
            s[nt][2] = ex2(s[nt][2] - m_hi);
            s[nt][3] = ex2(s[nt][3] - m_hi);
            sum_lo += s[nt][0] + s[nt][1];
            sum_hi += s[nt][2] + s[nt][3];
            o[nt][0] *= alpha_lo; o[nt][1] *= alpha_lo;
            o[nt][2] *= alpha_hi; o[nt][3] *= alpha_hi;
        }
        sum_lo += __shfl_xor_sync(0xffffffffu, sum_lo, 1);
        sum_lo += __shfl_xor_sync(0xffffffffu, sum_lo, 2);
        sum_hi += __shfl_xor_sync(0xffffffffu, sum_hi, 1);
        sum_hi += __shfl_xor_sync(0xffffffffu, sum_hi, 2);
        l_lo = l_lo * alpha_lo + sum_lo;
        l_hi = l_hi * alpha_hi + sum_hi;

        // ---- O += P V ----
#pragma unroll
        for (int ks = 0; ks < 4; ks++) {
            unsigned af[4];
            af[0] = pack_h2(s[2 * ks][0],     s[2 * ks][1]);
            af[1] = pack_h2(s[2 * ks][2],     s[2 * ks][3]);
            af[2] = pack_h2(s[2 * ks + 1][0], s[2 * ks + 1][1]);
            af[3] = pack_h2(s[2 * ks + 1][2], s[2 * ks + 1][3]);
#pragma unroll
            for (int dtp = 0; dtp < 4; dtp++) {
                unsigned vf[4];
                ldsm4t(vf, st + vOff + (unsigned)(ks * 16 * STH * 2) + (unsigned)(dtp * 32));
                mma_f16(o[2 * dtp],     af, vf[0], vf[1]);
                mma_f16(o[2 * dtp + 1], af, vf[2], vf[3]);
            }
        }
        // no end-of-loop barrier (depth-2 prefetch schedule makes it safe)
    }

    // ---- epilogue: normalize, write fp16 [B, N, H*D] ----
    float inv_lo = 1.0f / l_lo;
    float inv_hi = 1.0f / l_hi;
#pragma unroll
    for (int nt = 0; nt < 8; nt++) {
        int r = q0 + qr + lg;
        int c = h * HD + nt * 8 + (lt << 1);
        __half2 v0 = __floats2half2_rn(o[nt][0] * inv_lo, o[nt][1] * inv_lo);
        __half2 v1 = __floats2half2_rn(o[nt][2] * inv_hi, o[nt][3] * inv_hi);
        *(__half2*)&Out[(size_t)(b * SEQ + r) * C_DIM + c]     = v0;
        *(__half2*)&Out[(size_t)(b * SEQ + r + 8) * C_DIM + c] = v1;
    }
}

// ---------------------------------------------------------------------------
extern "C" void kernel_launch(void* const* d_in, const int* in_sizes, int n_in,
                              void* d_out, int out_size)
{
    const float* x    = (const float*)d_in[0];
    const float* Wqkv = (const float*)d_in[1];
    const float* Wout = (const float*)d_in[2];
    const float* bout = (const float*)d_in[3];
    float* out = (float*)d_out;

    float *qkv;
    __half *Qh, *Kh, *Vh, *attnh, *xh, *wqkvh, *wouth;
    cudaGetSymbolAddress((void**)&qkv,   g_qkv);
    cudaGetSymbolAddress((void**)&Qh,    g_Qh);
    cudaGetSymbolAddress((void**)&Kh,    g_Kh);
    cudaGetSymbolAddress((void**)&Vh,    g_Vh);
    cudaGetSymbolAddress((void**)&attnh, g_attnh);
    cudaGetSymbolAddress((void**)&xh,    g_xh);
    cudaGetSymbolAddress((void**)&wqkvh, g_wqkvh);
    cudaGetSymbolAddress((void**)&wouth, g_wouth);

    // 0) Prep: fp16 operand conversion + RoPE tables (single launch)
    prep_all<<<(NPREP + 255) / 256, 256>>>(
        (const float4*)x, (__half2*)xh,
        (const float4*)Wqkv, (__half2*)wqkvh,
        (const float4*)Wout, (__half2*)wouth);

    cudaFuncSetAttribute(gemm_f16_db,
                         cudaFuncAttributeMaxDynamicSharedMemorySize,
                         GEMM_SMEM_BYTES);

    // 1) QKV projection (fp16 in, fp32 out)
    gemm_f16_db<<<dim3(3 * C_DIM / GBN, M_ROWS / GBM), 256, GEMM_SMEM_BYTES>>>(
        xh, wqkvh, qkv, M_ROWS, 3 * C_DIM, C_DIM, nullptr);

    // 2) RoPE + transpose (Q pre-scaled by 0.125*log2e)
    {
        int total = BATCH * HEADS * SEQ * 16;
        rope_transpose<<<(total + 255) / 256, 256>>>(qkv, Qh, Kh, Vh);
    }

    // 3) Flash attention (R13-proven body)
    cudaFuncSetAttribute(attn_f16,
                         cudaFuncAttributeMaxDynamicSharedMemorySize,
                         ATTN_SMEM_BYTES);
    attn_f16<<<dim3(SEQ / QTILE, HEADS, BATCH), 256, ATTN_SMEM_BYTES>>>(
        Qh, Kh, Vh, attnh);

    // 4) Output projection (fp16 in, fp32 out + bias)
    gemm_f16_db<<<dim3(C_DIM / GBN, M_ROWS / GBM), 256, GEMM_SMEM_BYTES>>>(
        attnh, wouth, out, M_ROWS, C_DIM, C_DIM, bout);
}

// round 17
// speedup vs baseline: 1.0797x; 1.0797x over previous
#include <cuda_runtime.h>
#include <cuda_fp16.h>
#include <math.h>

// Problem constants
#define C_DIM   1024
#define HEADS   16
#define HD      64
#define BATCH   2
#define SEQ     2048
#define M_ROWS  (BATCH*SEQ)        // 4096

// Scratch (device globals: no allocation allowed)
__device__ float  g_qkv[(size_t)M_ROWS * 3 * C_DIM];          // [4096, 3072] fp32
__device__ __half g_Qh[(size_t)BATCH*HEADS*SEQ*HD];           // [B,H,N,D] fp16, pre-scaled 0.125*log2e
__device__ __half g_Kh[(size_t)BATCH*HEADS*SEQ*HD];
__device__ __half g_Vh[(size_t)BATCH*HEADS*SEQ*HD];
__device__ __half g_attnh[(size_t)M_ROWS * C_DIM];            // [B,N,H*D] fp16
__device__ __half g_xh[(size_t)M_ROWS * C_DIM];               // x fp16
__device__ __half g_wqkvh[(size_t)3 * C_DIM * C_DIM];         // Wqkv fp16
__device__ __half g_wouth[(size_t)C_DIM * C_DIM];             // Wout fp16
__device__ float  g_cos[SEQ * 32];
__device__ float  g_sin[SEQ * 32];

// ---------------------------------------------------------------------------
// helpers
// ---------------------------------------------------------------------------
__device__ __forceinline__ unsigned pack_h2(float lo, float hi) {
    unsigned r;
    asm("cvt.rn.f16x2.f32 %0, %1, %2;" : "=r"(r) : "f"(hi), "f"(lo));
    return r;
}

__device__ __forceinline__ float ex2(float x) {
    float r;
    asm("ex2.approx.f32 %0, %1;" : "=f"(r) : "f"(x));
    return r;
}

__device__ __forceinline__ void mma_f16(float* d, const unsigned* a, unsigned b0, unsigned b1) {
    asm volatile(
        "mma.sync.aligned.m16n8k16.row.col.f32.f16.f16.f32 "
        "{%0,%1,%2,%3}, {%4,%5,%6,%7}, {%8,%9}, {%0,%1,%2,%3};\n"
        : "+f"(d[0]), "+f"(d[1]), "+f"(d[2]), "+f"(d[3])
        : "r"(a[0]), "r"(a[1]), "r"(a[2]), "r"(a[3]), "r"(b0), "r"(b1));
}

__device__ __forceinline__ void ldsm4(unsigned* r, unsigned addr) {
    asm volatile(
        "ldmatrix.sync.aligned.m8n8.x4.shared.b16 {%0,%1,%2,%3}, [%4];"
        : "=r"(r[0]), "=r"(r[1]), "=r"(r[2]), "=r"(r[3]) : "r"(addr));
}
__device__ __forceinline__ void ldsm4t(unsigned* r, unsigned addr) {
    asm volatile(
        "ldmatrix.sync.aligned.m8n8.x4.trans.shared.b16 {%0,%1,%2,%3}, [%4];"
        : "=r"(r[0]), "=r"(r[1]), "=r"(r[2]), "=r"(r[3]) : "r"(addr));
}

__device__ __forceinline__ void cp_async16(unsigned saddr, const void* gaddr) {
    asm volatile("cp.async.cg.shared.global [%0], [%1], 16;" :: "r"(saddr), "l"(gaddr));
}
#define CP_COMMIT() asm volatile("cp.async.commit_group;")
#define CP_WAIT0()  asm volatile("cp.async.wait_group 0;")

// ---------------------------------------------------------------------------
// fp32 -> fp16 conversion (operand prep)
// ---------------------------------------------------------------------------
__global__ void to_half(const float4* __restrict__ in, __half2* __restrict__ out, int n4)
{
    int i = blockIdx.x * blockDim.x + threadIdx.x;
    if (i < n4) {
        float4 v = in[i];
        out[2 * i]     = __floats2half2_rn(v.x, v.y);
        out[2 * i + 1] = __floats2half2_rn(v.z, v.w);
    }
}

// ---------------------------------------------------------------------------
// fp16 GEMM (NT), cp.async 2-stage double-buffered, ldmatrix fragments.
// C[M,N](fp32) = A[M,K](fp16) * B[N,K]^T(fp16) (+ bias)
// ---------------------------------------------------------------------------
#define GBM 128
#define GBN 128
#define GBK 64
#define GSH 72
#define GSTAGE_BYTES ((GBM + GBN) * GSH * 2)    // 36864
#define GEMM_SMEM_BYTES (2 * GSTAGE_BYTES)      // 73728

__global__ __launch_bounds__(256, 2)
void gemm_f16_db(const __half* __restrict__ A, const __half* __restrict__ B,
                 float* __restrict__ C, int M, int N, int K,
                 const float* __restrict__ bias)
{
    extern __shared__ __half gsm[];

    const int tid  = threadIdx.x;
    const int lane = tid & 31;
    const int warp = tid >> 5;
    const int wm   = (warp >> 2) * 64;
    const int wn   = (warp & 3) * 32;
    const int m0   = blockIdx.y * GBM;
    const int n0   = blockIdx.x * GBN;
    const int lg   = lane >> 2;
    const int lt   = lane & 3;
    const int t8   = lane >> 3;
    const int rr   = lane & 7;

    const unsigned sA = (unsigned)__cvta_generic_to_shared(gsm);
    const unsigned sB = sA + GBM * GSH * 2;

    unsigned aab[4];
#pragma unroll
    for (int mt = 0; mt < 4; mt++)
        aab[mt] = sA + 2u * ((wm + mt * 16 + (t8 & 1) * 8 + rr) * GSH + (t8 >> 1) * 8);
    unsigned bbb[2];
#pragma unroll
    for (int ntp = 0; ntp < 2; ntp++)
        bbb[ntp] = sB + 2u * ((wn + ntp * 16 + (t8 >> 1) * 8 + rr) * GSH + (t8 & 1) * 8);

    float acc[4][4][4];
#pragma unroll
    for (int mt = 0; mt < 4; mt++)
#pragma unroll
        for (int nt = 0; nt < 4; nt++)
#pragma unroll
            for (int j = 0; j < 4; j++) acc[mt][nt][j] = 0.f;

    const int T = K / GBK;

    {
#pragma unroll
        for (int i = 0; i < 4; i++) {
            int e = tid + i * 256;
            int r = e >> 3, c8 = (e & 7) << 3;
            cp_async16(sA + 2u * (r * GSH + c8), &A[(size_t)(m0 + r) * K + c8]);
            cp_async16(sB + 2u * (r * GSH + c8), &B[(size_t)(n0 + r) * K + c8]);
        }
        CP_COMMIT();
    }

    for (int t = 0; t < T; t++) {
        const unsigned soff = (unsigned)(t & 1) * GSTAGE_BYTES;
        CP_WAIT0();
        __syncthreads();

        if (t + 1 < T) {
            const unsigned snext = (unsigned)((t + 1) & 1) * GSTAGE_BYTES;
            const int k0 = (t + 1) * GBK;
#pragma unroll
            for (int i = 0; i < 4; i++) {
                int e = tid + i * 256;
                int r = e >> 3, c8 = (e & 7) << 3;
                cp_async16(sA + snext + 2u * (r * GSH + c8),
                           &A[(size_t)(m0 + r) * K + k0 + c8]);
                cp_async16(sB + snext + 2u * (r * GSH + c8),
                           &B[(size_t)(n0 + r) * K + k0 + c8]);
            }
            CP_COMMIT();
        }

#pragma unroll
        for (int ks = 0; ks < 4; ks++) {
            unsigned af[4][4], bf[2][4];
#pragma unroll
            for (int mt = 0; mt < 4; mt++) ldsm4(af[mt], aab[mt] + soff + ks * 32);
#pragma unroll
            for (int ntp = 0; ntp < 2; ntp++) ldsm4(bf[ntp], bbb[ntp] + soff + ks * 32);
#pragma unroll
            for (int mt = 0; mt < 4; mt++)
#pragma unroll
                for (int nt = 0; nt < 4; nt++)
                    mma_f16(acc[mt][nt], af[mt],
                            bf[nt >> 1][(nt & 1) * 2], bf[nt >> 1][(nt & 1) * 2 + 1]);
        }
        __syncthreads();
    }

#pragma unroll
    for (int mt = 0; mt < 4; mt++) {
#pragma unroll
        for (int nt = 0; nt < 4; nt++) {
            int r = m0 + wm + mt * 16 + lg;
            int c = n0 + wn + nt * 8 + (lt << 1);
            float b0 = bias ? bias[c] : 0.f;
            float b1 = bias ? bias[c + 1] : 0.f;
            float2 v0 = make_float2(acc[mt][nt][0] + b0, acc[mt][nt][1] + b1);
            float2 v1 = make_float2(acc[mt][nt][2] + b0, acc[mt][nt][3] + b1);
            *(float2*)&C[(size_t)r * N + c]       = v0;
            *(float2*)&C[(size_t)(r + 8) * N + c] = v1;
        }
    }
}

// ---------------------------------------------------------------------------
// RoPE cos/sin table
// ---------------------------------------------------------------------------
__global__ void rope_table()
{
    int idx = blockIdx.x * blockDim.x + threadIdx.x;
    if (idx >= SEQ * 32) return;
    int i = idx & 31;
    int n = idx >> 5;
    float inv_freq = (float)pow(10000.0, -(double)i / 32.0);
    float phase = (float)n * inv_freq;
    g_cos[idx] = (float)cos((double)phase);
    g_sin[idx] = (float)sin((double)phase);
}

// ---------------------------------------------------------------------------
// RoPE + transpose (pair-symmetric, vectorized). Q pre-scaled by
// 0.125 * log2(e) so the attention kernel can use ex2 directly.
// ---------------------------------------------------------------------------
#define QSCALE 0.18033688011112042f   // 0.125 * log2(e)

__global__ void rope_transpose(const float* __restrict__ qkv,
                               __half* __restrict__ Q, __half* __restrict__ K,
                               __half* __restrict__ V)
{
    int idx = blockIdx.x * blockDim.x + threadIdx.x;   // over B*H*N*16
    if (idx >= BATCH * HEADS * SEQ * 16) return;
    int i2 = idx & 15;
    int n  = (idx >> 4) & (SEQ - 1);
    int h  = (idx >> 15) & (HEADS - 1);
    int b  = idx >> 19;

    const size_t mrow = (size_t)(b * SEQ + n) * (3 * C_DIM);
    const int col = h * HD + 2 * i2;

    float2 qlo = *(const float2*)&qkv[mrow + col];
    float2 qhi = *(const float2*)&qkv[mrow + col + 32];
    float2 klo = *(const float2*)&qkv[mrow + C_DIM + col];
    float2 khi = *(const float2*)&qkv[mrow + C_DIM + col + 32];
    float2 vlo = *(const float2*)&qkv[mrow + 2 * C_DIM + col];
    float2 vhi = *(const float2*)&qkv[mrow + 2 * C_DIM + col + 32];

    float2 cc = *(const float2*)&g_cos[n * 32 + 2 * i2];
    float2 ss = *(const float2*)&g_sin[n * 32 + 2 * i2];

    size_t o = ((size_t)(b * HEADS + h) * SEQ + n) * HD + 2 * i2;

    *(__half2*)&Q[o]      = __floats2half2_rn((qlo.x * cc.x - qhi.x * ss.x) * QSCALE,
                                              (qlo.y * cc.y - qhi.y * ss.y) * QSCALE);
    *(__half2*)&Q[o + 32] = __floats2half2_rn((qhi.x * cc.x + qlo.x * ss.x) * QSCALE,
                                              (qhi.y * cc.y + qlo.y * ss.y) * QSCALE);
    *(__half2*)&K[o]      = __floats2half2_rn(klo.x * cc.x - khi.x * ss.x,
                                              klo.y * cc.y - khi.y * ss.y);
    *(__half2*)&K[o + 32] = __floats2half2_rn(khi.x * cc.x + klo.x * ss.x,
                                              khi.y * cc.y + klo.y * ss.y);
    *(__half2*)&V[o]      = __floats2half2_rn(vlo.x, vlo.y);
    *(__half2*)&V[o + 32] = __floats2half2_rn(vhi.x, vhi.y);
}

// ---------------------------------------------------------------------------
// Flash attention (R13 structure — proven 294.4us):
//  - full fp16 mma, Q fragments hoisted, cp.async double-buffered KV
//  - softmax batched phase w/ online max, in the log2 domain (bare ex2)
//  - single __syncthreads per tile (top barrier is sufficient w/ 2 stages)
// ---------------------------------------------------------------------------
#define QTILE 128
#define KTILE 64
#define STH   72
#define Q_BYTES   (QTILE * STH * 2)
#define KV_STAGE  (2 * KTILE * STH * 2)
#define ATTN_SMEM_BYTES (Q_BYTES + 2 * KV_STAGE)  // 55296

__global__ __launch_bounds__(256)
void attn_f16(const __half* __restrict__ Q, const __half* __restrict__ K,
              const __half* __restrict__ V, __half* __restrict__ Out)
{
    extern __shared__ __half hsm[];

    const int tid  = threadIdx.x;
    const int lane = tid & 31;
    const int warp = tid >> 5;
    const int lg   = lane >> 2;
    const int lt   = lane & 3;
    const int t8   = lane >> 3;
    const int rr   = lane & 7;
    const int b = blockIdx.z, h = blockIdx.y;
    const int q0 = blockIdx.x * QTILE;
    const int qr = warp * 16;

    const unsigned sQ  = (unsigned)__cvta_generic_to_shared(hsm);
    const unsigned sKV = sQ + Q_BYTES;

    const __half* Qb = Q + (size_t)(b * HEADS + h) * SEQ * HD;
    const __half* Kb = K + (size_t)(b * HEADS + h) * SEQ * HD;
    const __half* Vb = V + (size_t)(b * HEADS + h) * SEQ * HD;

    const unsigned aQ = sQ + 2u * ((qr + (t8 & 1) * 8 + rr) * STH + (t8 >> 1) * 8);
    const unsigned kOff = 2u * (((t8 >> 1) * 8 + rr) * STH + (t8 & 1) * 8);
    const unsigned vOff = 2u * ((8 * (t8 & 1) + rr) * STH + 8 * (t8 >> 1));

    // Q tile fill
#pragma unroll
    for (int i = 0; i < 4; i++) {
        int e = tid + i * 256;
        int r = e >> 3, c8 = (e & 7) << 3;
        *(uint4*)&hsm[r * STH + c8] = *(const uint4*)&Qb[(size_t)(q0 + r) * HD + c8];
    }

    // KV tile 0 prefetch
    {
        const unsigned st = sKV;
#pragma unroll
        for (int i = 0; i < 2; i++) {
            int e = tid + i * 256;
            int r = e >> 3, c8 = (e & 7) << 3;
            cp_async16(st + 2u * (r * STH + c8), &Kb[(size_t)r * HD + c8]);
            cp_async16(st + (unsigned)(KTILE * STH * 2) + 2u * (r * STH + c8),
                       &Vb[(size_t)r * HD + c8]);
        }
        CP_COMMIT();
    }

    // Hoist Q fragments (tile-invariant)
    __syncthreads();
    unsigned aq[4][4];
#pragma unroll
    for (int ks = 0; ks < 4; ks++) ldsm4(aq[ks], aQ + ks * 32);

    float o[8][4];
#pragma unroll
    for (int nt = 0; nt < 8; nt++)
#pragma unroll
        for (int j = 0; j < 4; j++) o[nt][j] = 0.f;
    float m_lo = -1e30f, m_hi = -1e30f, l_lo = 0.f, l_hi = 0.f;

    const int T = SEQ / KTILE;
    for (int t = 0; t < T; t++) {
        const unsigned st = sKV + (unsigned)(t & 1) * KV_STAGE;
        CP_WAIT0();
        __syncthreads();

        if (t + 1 < T) {
            const unsigned sn = sKV + (unsigned)((t + 1) & 1) * KV_STAGE;
            const int k0 = (t + 1) * KTILE;
#pragma unroll
            for (int i = 0; i < 2; i++) {
                int e = tid + i * 256;
                int r = e >> 3, c8 = (e & 7) << 3;
                cp_async16(sn + 2u * (r * STH + c8), &Kb[(size_t)(k0 + r) * HD + c8]);
                cp_async16(sn + (unsigned)(KTILE * STH * 2) + 2u * (r * STH + c8),
                           &Vb[(size_t)(k0 + r) * HD + c8]);
            }
            CP_COMMIT();
        }

        // ---- S' = (log2e/8) Q K^T  (log2 domain) ----
        float s[8][4];
#pragma unroll
        for (int nt = 0; nt < 8; nt++)
#pragma unroll
            for (int j = 0; j < 4; j++) s[nt][j] = 0.f;

#pragma unroll
        for (int ks = 0; ks < 4; ks++) {
#pragma unroll
            for (int ntp = 0; ntp < 4; ntp++) {
                unsigned kf[4];
                ldsm4(kf, st + kOff + (unsigned)(ntp * 16 * STH * 2) + ks * 32);
                mma_f16(s[2 * ntp],     aq[ks], kf[0], kf[1]);
                mma_f16(s[2 * ntp + 1], aq[ks], kf[2], kf[3]);
            }
        }

        // ---- online softmax (log2 domain, batched phase) ----
        float rmax_lo = -1e30f, rmax_hi = -1e30f;
#pragma unroll
        for (int nt = 0; nt < 8; nt++) {
            rmax_lo = fmaxf(rmax_lo, fmaxf(s[nt][0], s[nt][1]));
            rmax_hi = fmaxf(rmax_hi, fmaxf(s[nt][2], s[nt][3]));
        }
        rmax_lo = fmaxf(rmax_lo, __shfl_xor_sync(0xffffffffu, rmax_lo, 1));
        rmax_lo = fmaxf(rmax_lo, __shfl_xor_sync(0xffffffffu, rmax_lo, 2));
        rmax_hi = fmaxf(rmax_hi, __shfl_xor_sync(0xffffffffu, rmax_hi, 1));
        rmax_hi = fmaxf(rmax_hi, __shfl_xor_sync(0xffffffffu, rmax_hi, 2));

        float mn_lo = fmaxf(m_lo, rmax_lo);
        float mn_hi = fmaxf(m_hi, rmax_hi);
        float alpha_lo = ex2(m_lo - mn_lo);
        float alpha_hi = ex2(m_hi - mn_hi);
        m_lo = mn_lo; m_hi = mn_hi;

        float sum_lo = 0.f, sum_hi = 0.f;
#pragma unroll
        for (int nt = 0; nt < 8; nt++) {
            s[nt][0] = ex2(s[nt][0] - m_lo);
            s[nt][1] = ex2(s[nt][1] - m_lo);
            s[nt][2] = ex2(s[nt][2] - m_hi);
            s[nt][3] = ex2(s[nt][3] - m_hi);
            sum_lo += s[nt][0] + s[nt][1];
            sum_hi += s[nt][2] + s[nt][3];
            o[nt][0] *= alpha_lo; o[nt][1] *= alpha_lo;
            o[nt][2] *= alpha_hi; o[nt][3] *= alpha_hi;
        }
        sum_lo += __shfl_xor_sync(0xffffffffu, sum_lo, 1);
        sum_lo += __shfl_xor_sync(0xffffffffu, sum_lo, 2);
        sum_hi += __shfl_xor_sync(0xffffffffu, sum_hi, 1);
        sum_hi += __shfl_xor_sync(0xffffffffu, sum_hi, 2);
        l_lo = l_lo * alpha_lo + sum_lo;
        l_hi = l_hi * alpha_hi + sum_hi;

        // ---- O += P V ----
        const unsigned stV = st + (unsigned)(KTILE * STH * 2) + vOff;
#pragma unroll
        for (int ks = 0; ks < 4; ks++) {
            unsigned af[4];
            af[0] = pack_h2(s[2 * ks][0],     s[2 * ks][1]);
            af[1] = pack_h2(s[2 * ks][2],     s[2 * ks][3]);
            af[2] = pack_h2(s[2 * ks + 1][0], s[2 * ks + 1][1]);
            af[3] = pack_h2(s[2 * ks + 1][2], s[2 * ks + 1][3]);
#pragma unroll
            for (int dtp = 0; dtp < 4; dtp++) {
                unsigned vf[4];
                ldsm4t(vf, stV + (unsigned)(ks * 16 * STH * 2) + (unsigned)(dtp * 32));
                mma_f16(o[2 * dtp],     af, vf[0], vf[1]);
                mma_f16(o[2 * dtp + 1], af, vf[2], vf[3]);
            }
        }
        // NOTE: no end-of-loop __syncthreads — the top barrier of the next
        // iteration is sufficient with 2-stage buffering (prefetch for t+2 is
        // issued only after all warps pass the t+1 top barrier, i.e. after
        // all reads of stage t completed).
    }

    // ---- epilogue: normalize, write fp16 [B, N, H*D] ----
    float inv_lo = 1.0f / l_lo;
    float inv_hi = 1.0f / l_hi;
#pragma unroll
    for (int nt = 0; nt < 8; nt++) {
        int r = q0 + qr + lg;
        int c = h * HD + nt * 8 + (lt << 1);
        __half2 v0 = __floats2half2_rn(o[nt][0] * inv_lo, o[nt][1] * inv_lo);
        __half2 v1 = __floats2half2_rn(o[nt][2] * inv_hi, o[nt][3] * inv_hi);
        *(__half2*)&Out[(size_t)(b * SEQ + r) * C_DIM + c]     = v0;
        *(__half2*)&Out[(size_t)(b * SEQ + r + 8) * C_DIM + c] = v1;
    }
}

// ---------------------------------------------------------------------------
extern "C" void kernel_launch(void* const* d_in, const int* in_sizes, int n_in,
                              void* d_out, int out_size)
{
    const float* x    = (const float*)d_in[0];
    const float* Wqkv = (const float*)d_in[1];
    const float* Wout = (const float*)d_in[2];
    const float* bout = (const float*)d_in[3];
    float* out = (float*)d_out;

    float *qkv;
    __half *Qh, *Kh, *Vh, *attnh, *xh, *wqkvh, *wouth;
    cudaGetSymbolAddress((void**)&qkv,   g_qkv);
    cudaGetSymbolAddress((void**)&Qh,    g_Qh);
    cudaGetSymbolAddress((void**)&Kh,    g_Kh);
    cudaGetSymbolAddress((void**)&Vh,    g_Vh);
    cudaGetSymbolAddress((void**)&attnh, g_attnh);
    cudaGetSymbolAddress((void**)&xh,    g_xh);
    cudaGetSymbolAddress((void**)&wqkvh, g_wqkvh);
    cudaGetSymbolAddress((void**)&wouth, g_wouth);

    // 0) RoPE tables + fp16 operand prep
    rope_table<<<(SEQ * 32 + 255) / 256, 256>>>();
    {
        int n4;
        n4 = M_ROWS * C_DIM / 4;
        to_half<<<(n4 + 255) / 256, 256>>>((const float4*)x, (__half2*)xh, n4);
        n4 = 3 * C_DIM * C_DIM / 4;
        to_half<<<(n4 + 255) / 256, 256>>>((const float4*)Wqkv, (__half2*)wqkvh, n4);
        n4 = C_DIM * C_DIM / 4;
        to_half<<<(n4 + 255) / 256, 256>>>((const float4*)Wout, (__half2*)wouth, n4);
    }

    cudaFuncSetAttribute(gemm_f16_db,
                         cudaFuncAttributeMaxDynamicSharedMemorySize,
                         GEMM_SMEM_BYTES);

    // 1) QKV projection (fp16 in, fp32 out)
    gemm_f16_db<<<dim3(3 * C_DIM / GBN, M_ROWS / GBM), 256, GEMM_SMEM_BYTES>>>(
        xh, wqkvh, qkv, M_ROWS, 3 * C_DIM, C_DIM, nullptr);

    // 2) RoPE + transpose (Q pre-scaled by 0.125*log2e)
    {
        int total = BATCH * HEADS * SEQ * 16;
        rope_transpose<<<(total + 255) / 256, 256>>>(qkv, Qh, Kh, Vh);
    }

    // 3) Flash attention (R13 structure, log2-domain softmax, 1 barrier/tile)
    cudaFuncSetAttribute(attn_f16,
                         cudaFuncAttributeMaxDynamicSharedMemorySize,
                         ATTN_SMEM_BYTES);
    attn_f16<<<dim3(SEQ / QTILE, HEADS, BATCH), 256, ATTN_SMEM_BYTES>>>(
        Qh, Kh, Vh, attnh);

    // 4) Output projection (fp16 in, fp32 out + bias)
    gemm_f16_db<<<dim3(C_DIM / GBN, M_ROWS / GBM), 256, GEMM_SMEM_BYTES>>>(
        attnh, wouth, out, M_ROWS, C_DIM, C_DIM, bout);
}